// round 11
// baseline (speedup 1.0000x reference)
#include <cuda_runtime.h>
#include <cuda_bf16.h>
#include <math.h>

// Problem constants
#define NXD 320
#define GD  640            // OS*NX
#define NCOIL 8
#define NFRAME 8
#define MS 65536
#define NPIX (NXD*NXD)     // 102400

#define PADI8(i) ((i) + ((i) >> 3))
#define NP8 728            // PADI8(639)=718, padded to 728 (mod 32 == 24)

// Scratch (allocations are forbidden -> __device__ globals)
// d_grid layout: [t][i][j][coil] as float2, declared float4 for 16B alignment.
__device__ float4 d_grid4[(size_t)NFRAME*GD*GD*NCOIL/2];   // ~210 MB
__device__ float2 d_tmp1[(size_t)NFRAME*NCOIL*GD*NXD];     // ~105 MB  [img][r][j]
__device__ float2 d_imt[NFRAME*NPIX];                      // 8 x 320 x 320 (red-accumulated)

// csm pointers for fused pass2 (set once per launch sequence; the harness
// passes the same device buffers on every replay, so this is deterministic).
__device__ const float* c_csr;
__device__ const float* c_csi;

// ---------------- radix-8 butterfly (sign +i) ----------------
#define RADIX8_BODY() \
    float t0r=a0r+a4r, t0i=a0i+a4i; \
    float t1r=a0r-a4r, t1i=a0i-a4i; \
    float t2r=a2r+a6r, t2i=a2i+a6i; \
    float t3r=a2r-a6r, t3i=a2i-a6i; \
    float E0r=t0r+t2r, E0i=t0i+t2i; \
    float E2r=t0r-t2r, E2i=t0i-t2i; \
    float E1r=t1r-t3i, E1i=t1i+t3r; \
    float E3r=t1r+t3i, E3i=t1i-t3r; \
    float u0r=a1r+a5r, u0i=a1i+a5i; \
    float u1r=a1r-a5r, u1i=a1i-a5i; \
    float u2r=a3r+a7r, u2i=a3i+a7i; \
    float u3r=a3r-a7r, u3i=a3i-a7i; \
    float O0r=u0r+u2r, O0i=u0i+u2i; \
    float O2r=u0r-u2r, O2i=u0i-u2i; \
    float O1r=u1r-u3i, O1i=u1i+u3r; \
    float O3r=u1r+u3i, O3i=u1i-u3r; \
    const float RS2 = 0.70710678118654752440f; \
    float W1r = RS2*(O1r - O1i), W1i = RS2*(O1r + O1i); \
    float W2r = -O2i,            W2i = O2r; \
    float W3r = -RS2*(O3r + O3i), W3i = RS2*(O3r - O3i); \
    float b0r=E0r+O0r, b0i=E0i+O0i, b4r=E0r-O0r, b4i=E0i-O0i; \
    float b1r=E1r+W1r, b1i=E1i+W1i, b5r=E1r-W1r, b5i=E1i-W1i; \
    float b2r=E2r+W2r, b2i=E2i+W2i, b6r=E2r-W2r, b6i=E2i-W2i; \
    float b3r=E3r+W3r, b3i=E3i+W3i, b7r=E3r-W3r, b7i=E3i-W3i;

#define CMULW(br,bi,cr,ci, outr,outi) { outr = br*cr - bi*ci; outi = br*ci + bi*cr; }

// ---------------- stage 1: radix-8, S=1, n=640 ----------------
__device__ __forceinline__ void s1_r8(const float* __restrict__ sr, const float* __restrict__ si,
                                      float* __restrict__ dr, float* __restrict__ di, int lt)
{
    float a0r=sr[PADI8(lt)],     a0i=si[PADI8(lt)];
    float a1r=sr[PADI8(lt+80)],  a1i=si[PADI8(lt+80)];
    float a2r=sr[PADI8(lt+160)], a2i=si[PADI8(lt+160)];
    float a3r=sr[PADI8(lt+240)], a3i=si[PADI8(lt+240)];
    float a4r=sr[PADI8(lt+320)], a4i=si[PADI8(lt+320)];
    float a5r=sr[PADI8(lt+400)], a5i=si[PADI8(lt+400)];
    float a6r=sr[PADI8(lt+480)], a6i=si[PADI8(lt+480)];
    float a7r=sr[PADI8(lt+560)], a7i=si[PADI8(lt+560)];
    RADIX8_BODY();

    float base = 6.2831853071795864769f * (1.0f/640.0f) * (float)lt;
    float c1,s1;  __sincosf(base, &s1, &c1);
    float c2=c1*c1-s1*s1, s2=2.0f*c1*s1;
    float c3=c1*c2-s1*s2, s3=c1*s2+s1*c2;
    float c4=c2*c2-s2*s2, s4=2.0f*c2*s2;
    float c5=c2*c3-s2*s3, s5=c2*s3+s2*c3;
    float c6=c3*c3-s3*s3, s6=2.0f*c3*s3;
    float c7=c3*c4-s3*s4, s7=c3*s4+s3*c4;

    int w = 8*lt;
    float xr, xi;
    dr[PADI8(w)]   = b0r;  di[PADI8(w)]   = b0i;
    CMULW(b1r,b1i,c1,s1,xr,xi); dr[PADI8(w+1)] = xr; di[PADI8(w+1)] = xi;
    CMULW(b2r,b2i,c2,s2,xr,xi); dr[PADI8(w+2)] = xr; di[PADI8(w+2)] = xi;
    CMULW(b3r,b3i,c3,s3,xr,xi); dr[PADI8(w+3)] = xr; di[PADI8(w+3)] = xi;
    CMULW(b4r,b4i,c4,s4,xr,xi); dr[PADI8(w+4)] = xr; di[PADI8(w+4)] = xi;
    CMULW(b5r,b5i,c5,s5,xr,xi); dr[PADI8(w+5)] = xr; di[PADI8(w+5)] = xi;
    CMULW(b6r,b6i,c6,s6,xr,xi); dr[PADI8(w+6)] = xr; di[PADI8(w+6)] = xi;
    CMULW(b7r,b7i,c7,s7,xr,xi); dr[PADI8(w+7)] = xr; di[PADI8(w+7)] = xi;
}

// ---------------- stage 2: radix-8, S=8, n=80 ----------------
__device__ __forceinline__ void s2_r8(const float* __restrict__ sr, const float* __restrict__ si,
                                      float* __restrict__ dr, float* __restrict__ di, int lt)
{
    int q = lt & 7, p = lt >> 3;
    float a0r=sr[PADI8(lt)],     a0i=si[PADI8(lt)];
    float a1r=sr[PADI8(lt+80)],  a1i=si[PADI8(lt+80)];
    float a2r=sr[PADI8(lt+160)], a2i=si[PADI8(lt+160)];
    float a3r=sr[PADI8(lt+240)], a3i=si[PADI8(lt+240)];
    float a4r=sr[PADI8(lt+320)], a4i=si[PADI8(lt+320)];
    float a5r=sr[PADI8(lt+400)], a5i=si[PADI8(lt+400)];
    float a6r=sr[PADI8(lt+480)], a6i=si[PADI8(lt+480)];
    float a7r=sr[PADI8(lt+560)], a7i=si[PADI8(lt+560)];
    RADIX8_BODY();

    float base = 6.2831853071795864769f * (1.0f/80.0f) * (float)p;
    float c1,s1;  __sincosf(base, &s1, &c1);
    float c2=c1*c1-s1*s1, s2=2.0f*c1*s1;
    float c3=c1*c2-s1*s2, s3=c1*s2+s1*c2;
    float c4=c2*c2-s2*s2, s4=2.0f*c2*s2;
    float c5=c2*c3-s2*s3, s5=c2*s3+s2*c3;
    float c6=c3*c3-s3*s3, s6=2.0f*c3*s3;
    float c7=c3*c4-s3*s4, s7=c3*s4+s3*c4;

    int w = 64*p + q;
    float xr, xi;
    dr[PADI8(w)]    = b0r;  di[PADI8(w)]    = b0i;
    CMULW(b1r,b1i,c1,s1,xr,xi); dr[PADI8(w+8)]  = xr; di[PADI8(w+8)]  = xi;
    CMULW(b2r,b2i,c2,s2,xr,xi); dr[PADI8(w+16)] = xr; di[PADI8(w+16)] = xi;
    CMULW(b3r,b3i,c3,s3,xr,xi); dr[PADI8(w+24)] = xr; di[PADI8(w+24)] = xi;
    CMULW(b4r,b4i,c4,s4,xr,xi); dr[PADI8(w+32)] = xr; di[PADI8(w+32)] = xi;
    CMULW(b5r,b5i,c5,s5,xr,xi); dr[PADI8(w+40)] = xr; di[PADI8(w+40)] = xi;
    CMULW(b6r,b6i,c6,s6,xr,xi); dr[PADI8(w+48)] = xr; di[PADI8(w+48)] = xi;
    CMULW(b7r,b7i,c7,s7,xr,xi); dr[PADI8(w+56)] = xr; di[PADI8(w+56)] = xi;
}

// ---------------- stage 3: radix-10, S=64, twiddle-free ----------------
#define DFT5M(x0r,x0i,x1r,x1i,x2r,x2i,x3r,x3i,x4r,x4i, X0r,X0i,X1r,X1i,X2r,X2i,X3r,X3i,X4r,X4i) { \
    const float C1 =  0.3090169943749474241f; \
    const float S1 =  0.9510565162951535721f; \
    const float C2 = -0.8090169943749474241f; \
    const float S2 =  0.5877852522924731292f; \
    float t1r=x1r+x4r, t1i=x1i+x4i, t2r=x1r-x4r, t2i=x1i-x4i; \
    float t3r=x2r+x3r, t3i=x2i+x3i, t4r=x2r-x3r, t4i=x2i-x3i; \
    X0r = x0r + t1r + t3r;  X0i = x0i + t1i + t3i; \
    float m1r = x0r + C1*t1r + C2*t3r, m1i = x0i + C1*t1i + C2*t3i; \
    float m2r = x0r + C2*t1r + C1*t3r, m2i = x0i + C2*t1i + C1*t3i; \
    float n1r = S1*t2r + S2*t4r, n1i = S1*t2i + S2*t4i; \
    float n2r = S2*t2r - S1*t4r, n2i = S2*t2i - S1*t4i; \
    X1r = m1r - n1i;  X1i = m1i + n1r; \
    X4r = m1r + n1i;  X4i = m1i - n1r; \
    X2r = m2r - n2i;  X2i = m2i + n2r; \
    X3r = m2r + n2i;  X3i = m2i - n2r; \
}

#define STAGE3_LOAD_AND_BFLY() \
    float a0r=sr[PADI8(lt)],     a0i=si[PADI8(lt)]; \
    float a1r=sr[PADI8(lt+64)],  a1i=si[PADI8(lt+64)]; \
    float a2r=sr[PADI8(lt+128)], a2i=si[PADI8(lt+128)]; \
    float a3r=sr[PADI8(lt+192)], a3i=si[PADI8(lt+192)]; \
    float a4r=sr[PADI8(lt+256)], a4i=si[PADI8(lt+256)]; \
    float a5r=sr[PADI8(lt+320)], a5i=si[PADI8(lt+320)]; \
    float a6r=sr[PADI8(lt+384)], a6i=si[PADI8(lt+384)]; \
    float a7r=sr[PADI8(lt+448)], a7i=si[PADI8(lt+448)]; \
    float a8r=sr[PADI8(lt+512)], a8i=si[PADI8(lt+512)]; \
    float a9r=sr[PADI8(lt+576)], a9i=si[PADI8(lt+576)]; \
    float E0r,E0i,E1r,E1i,E2r,E2i,E3r,E3i,E4r,E4i; \
    float O0r,O0i,O1r,O1i,O2r,O2i,O3r,O3i,O4r,O4i; \
    DFT5M(a0r,a0i,a2r,a2i,a4r,a4i,a6r,a6i,a8r,a8i, E0r,E0i,E1r,E1i,E2r,E2i,E3r,E3i,E4r,E4i); \
    DFT5M(a1r,a1i,a3r,a3i,a5r,a5i,a7r,a7i,a9r,a9i, O0r,O0i,O1r,O1i,O2r,O2i,O3r,O3i,O4r,O4i); \
    const float W1R=0.8090169943749474241f,  W1I=0.5877852522924731292f; \
    const float W2R=0.3090169943749474241f,  W2I=0.9510565162951535721f; \
    const float W3R=-0.3090169943749474241f, W3I=0.9510565162951535721f; \
    const float W4R=-0.8090169943749474241f, W4I=0.5877852522924731292f; \
    float P1r,P1i,P2r,P2i,P3r,P3i,P4r,P4i; \
    CMULW(O1r,O1i,W1R,W1I,P1r,P1i); \
    CMULW(O2r,O2i,W2R,W2I,P2r,P2i); \
    CMULW(O3r,O3i,W3R,W3I,P3r,P3i); \
    CMULW(O4r,O4i,W4R,W4I,P4r,P4i); \
    float b0r=E0r+O0r, b0i=E0i+O0i; \
    float b1r=E1r+P1r, b1i=E1i+P1i; \
    float b2r=E2r+P2r, b2i=E2i+P2i; \
    float b7r=E2r-P2r, b7i=E2i-P2i; \
    float b8r=E3r-P3r, b8i=E3i-P3i; \
    float b9r=E4r-P4r, b9i=E4i-P4i;

// deapodization inverse factor: 1/sinc^2((i-160)/640)
__device__ __forceinline__ float deapod_inv(int i)
{
    if (i == 160) return 1.0f;
    float px = 3.14159265358979324f * (float)(i - 160) * (1.0f/640.0f);
    float s = __sinf(px);
    float r = px / s;
    return r * r;
}

// ---------------- kernels ----------------
__global__ void k_set_csm(const float* csr, const float* csi)
{
    c_csr = csr;  c_csi = csi;
}

// Zeroes the grid AND d_imt (pass2 red-accumulates into d_imt).
__global__ void k_zero_all()
{
    unsigned i = blockIdx.x * blockDim.x + threadIdx.x;
    const unsigned n1 = (unsigned)(NFRAME*NCOIL) * GD * GD / 2;   // grid float4s
    const unsigned n2 = (unsigned)NFRAME * NPIX / 2;              // d_imt float4s
    if (i < n1) d_grid4[i] = make_float4(0.f,0.f,0.f,0.f);
    else if (i < n1 + n2) reinterpret_cast<float4*>(d_imt)[i - n1] = make_float4(0.f,0.f,0.f,0.f);
}

__device__ __forceinline__ void red_v4(float* p, float a, float b, float c, float d)
{
    asm volatile("red.global.add.v4.f32 [%0], {%1, %2, %3, %4};"
                 :: "l"(p), "f"(a), "f"(b), "f"(c), "f"(d) : "memory");
}
__device__ __forceinline__ void red_v2(float2* p, float re, float im)
{
    asm volatile("red.global.add.v2.f32 [%0], {%1, %2};" :: "l"(p), "f"(re), "f"(im) : "memory");
}

__global__ void k_scatter(const float* __restrict__ ksr, const float* __restrict__ ksi,
                          const float* __restrict__ traj, const float* __restrict__ dcf)
{
    int idx = blockIdx.x * blockDim.x + threadIdx.x;   // t*MS + m
    if (idx >= NFRAME * MS) return;
    int t = idx >> 16;
    int m = idx & (MS - 1);

    float u = (traj[m*2*NFRAME + 0*NFRAME + t] + 0.5f) * (float)GD;
    float v = (traj[m*2*NFRAME + 1*NFRAME + t] + 0.5f) * (float)GD;
    float w = dcf[m*NFRAME + t];

    float u0f = floorf(u), v0f = floorf(v);
    float du = u - u0f, dv = v - v0f;
    int i0 = (int)u0f; if (i0 >= GD) i0 -= GD;
    int j0 = (int)v0f; if (j0 >= GD) j0 -= GD;
    int i1 = i0 + 1; if (i1 >= GD) i1 -= GD;
    int j1 = j0 + 1; if (j1 >= GD) j1 -= GD;

    float wc[4];
    wc[0] = (1.0f-du)*(1.0f-dv)*w;
    wc[1] = du*(1.0f-dv)*w;
    wc[2] = (1.0f-du)*dv*w;
    wc[3] = du*dv*w;
    size_t oc[4];
    oc[0] = ((size_t)i0*GD + j0) * NCOIL;
    oc[1] = ((size_t)i1*GD + j0) * NCOIL;
    oc[2] = ((size_t)i0*GD + j1) * NCOIL;
    oc[3] = ((size_t)i1*GD + j1) * NCOIL;

    float kr[NCOIL], ki[NCOIL];
    #pragma unroll
    for (int c = 0; c < NCOIL; c++) { kr[c] = ksr[c*MS + m]; ki[c] = ksi[c*MS + m]; }

    float* gbase = (float*)(d_grid4) + (size_t)t * GD * GD * NCOIL * 2;
    #pragma unroll
    for (int k = 0; k < 4; k++) {
        float* p = gbase + oc[k]*2;
        float ww = wc[k];
        #pragma unroll
        for (int h = 0; h < 4; h++) {
            red_v4(p + 4*h, kr[2*h]*ww, ki[2*h]*ww, kr[2*h+1]*ww, ki[2*h+1]*ww);
        }
    }
}

// Pass 1: block = (t, row r, coil-group cg of 4). 4 concurrent 640-pt FFTs
// along j. Stage 3 streams cropped+shifted rows directly to global.
__global__ void __launch_bounds__(320, 3) k_fft_pass1()
{
    __shared__ float cR[4][NP8], cI[4][NP8];
    __shared__ float pR[4][NP8], pI[4][NP8];
    int b = blockIdx.x;
    int cg = b & 1;
    int tr = b >> 1;
    int t  = tr / GD;
    int r  = tr - t * GD;
    int tid = threadIdx.x;

    const float2* row = (const float2*)d_grid4 + ((size_t)(t*GD + r) * GD) * NCOIL + 4*cg;
    #pragma unroll
    for (int it = 0; it < 8; it++) {
        int idx = it * 320 + tid;
        int j  = idx >> 2;
        int cl = idx & 3;
        int jsh = (j < NXD) ? (j + NXD) : (j - NXD);
        float2 v = row[(size_t)j * NCOIL + cl];
        cR[cl][PADI8(jsh)] = v.x;  cI[cl][PADI8(jsh)] = v.y;
    }
    __syncthreads();

    int f  = tid / 80;
    int lt = tid - f * 80;

    s1_r8(cR[f], cI[f], pR[f], pI[f], lt);
    __syncthreads();
    s2_r8(pR[f], pI[f], cR[f], cI[f], lt);
    __syncthreads();

    if (lt < 64) {
        const float* sr = cR[f];
        const float* si = cI[f];
        STAGE3_LOAD_AND_BFLY();
        int c = 4*cg + f;
        float2* orow = d_tmp1 + ((size_t)(t*NCOIL + c) * GD + r) * NXD;
        orow[lt+160] = make_float2(b0r, b0i);                 // k=0
        orow[lt+224] = make_float2(b1r, b1i);                 // k=1
        if (lt < 32)  orow[lt+288] = make_float2(b2r, b2i);   // k=2
        if (lt >= 32) orow[lt-32]  = make_float2(b7r, b7i);   // k=7
        orow[lt+32]  = make_float2(b8r, b8i);                 // k=8
        orow[lt+96]  = make_float2(b9r, b9i);                 // k=9
    }
}

// Pass 2 FUSED with coil combine: block = (t, coil-half ch, 4 columns jb).
// Iterates 4 coils; per coil runs 4 column FFTs, accumulates conj(csm)*im in
// stage-3 registers. Deapod scale applied once at end; result red-added to d_imt.
__global__ void __launch_bounds__(320, 3) k_fft_pass2()
{
    __shared__ float cR[4][NP8], cI[4][NP8];
    __shared__ float pR[4][NP8], pI[4][NP8];
    int b  = blockIdx.x;
    int ch = b & 1;                       // coil half: coils ch*4 .. ch*4+3
    int jp = (b >> 1) % (NXD/4);
    int t  = b / (2*(NXD/4));
    int jb = jp * 4;
    int tid = threadIdx.x;
    int f  = tid / 80;
    int lt = tid - f * 80;
    int col = jb + f;

    // Per-thread accumulators (used by lt<64 threads): 6 output rows
    // (i2 covers k=2 for lt<32 and k=7 for lt>=32).
    float aR0=0.f,aI0=0.f, aR1=0.f,aI1=0.f, aR2=0.f,aI2=0.f;
    float aR4=0.f,aI4=0.f, aR5=0.f,aI5=0.f;

    int i0 = lt + 160, i1 = lt + 224, i4 = lt + 32, i5 = lt + 96;
    int i2 = (lt < 32) ? (lt + 288) : (lt - 32);

    #pragma unroll 1
    for (int it = 0; it < 4; it++) {
        int c = ch*4 + it;

        // Coalesced tile load (4 cols of coil c) with ifftshift on rows.
        const float2* base = d_tmp1 + ((size_t)(t*NCOIL + c) * GD) * NXD + jb;
        #pragma unroll
        for (int k = 0; k < 8; k++) {
            int idx = k * 320 + tid;
            int rr = idx >> 2;
            int cl = idx & 3;
            int rsh = (rr < NXD) ? (rr + NXD) : (rr - NXD);
            float2 v = base[(size_t)rr * NXD + cl];
            cR[cl][PADI8(rsh)] = v.x;  cI[cl][PADI8(rsh)] = v.y;
        }
        __syncthreads();

        s1_r8(cR[f], cI[f], pR[f], pI[f], lt);
        __syncthreads();
        s2_r8(pR[f], pI[f], cR[f], cI[f], lt);
        __syncthreads();

        if (lt < 64) {
            const float* sr = cR[f];
            const float* si = cI[f];
            STAGE3_LOAD_AND_BFLY();
            // conj(csm)*v accumulate (csm tiles are L2-resident after frame 0)
            const float* csr_b = c_csr + (size_t)c * NPIX + col;
            const float* csi_b = c_csi + (size_t)c * NPIX + col;
            float cr, ci;
            cr = csr_b[i0*NXD]; ci = csi_b[i0*NXD];
            aR0 += cr*b0r + ci*b0i;  aI0 += cr*b0i - ci*b0r;
            cr = csr_b[i1*NXD]; ci = csi_b[i1*NXD];
            aR1 += cr*b1r + ci*b1i;  aI1 += cr*b1i - ci*b1r;
            cr = csr_b[i2*NXD]; ci = csi_b[i2*NXD];
            if (lt < 32) { aR2 += cr*b2r + ci*b2i;  aI2 += cr*b2i - ci*b2r; }
            else         { aR2 += cr*b7r + ci*b7i;  aI2 += cr*b7i - ci*b7r; }
            cr = csr_b[i4*NXD]; ci = csi_b[i4*NXD];
            aR4 += cr*b8r + ci*b8i;  aI4 += cr*b8i - ci*b8r;
            cr = csr_b[i5*NXD]; ci = csi_b[i5*NXD];
            aR5 += cr*b9r + ci*b9i;  aI5 += cr*b9i - ci*b9r;
        }
        __syncthreads();   // protect cR before next coil's load
    }

    // Deapod + 1/(G*G) scale once, stage into pR/pI for coalesced store.
    if (lt < 64) {
        float sj = (1.0f/409600.0f) * deapod_inv(col);
        float* qr = pR[f];
        float* qi = pI[f];
        float s;
        s = sj*deapod_inv(i0); qr[PADI8(i0)] = aR0*s; qi[PADI8(i0)] = aI0*s;
        s = sj*deapod_inv(i1); qr[PADI8(i1)] = aR1*s; qi[PADI8(i1)] = aI1*s;
        s = sj*deapod_inv(i2); qr[PADI8(i2)] = aR2*s; qi[PADI8(i2)] = aI2*s;
        s = sj*deapod_inv(i4); qr[PADI8(i4)] = aR4*s; qi[PADI8(i4)] = aI4*s;
        s = sj*deapod_inv(i5); qr[PADI8(i5)] = aR5*s; qi[PADI8(i5)] = aI5*s;
    }
    __syncthreads();

    // Coalesced tile red-add into d_imt (two coil-halves accumulate).
    float2* obase = d_imt + (size_t)t * NPIX + jb;
    #pragma unroll
    for (int k = 0; k < 4; k++) {
        int idx = k * 320 + tid;
        int i  = idx >> 2;
        int cl = idx & 3;
        red_v2(&obase[(size_t)i * NXD + cl], pR[cl][PADI8(i)], pI[cl][PADI8(i)]);
    }
}

// Motion warp each frame and sum over frames.
__global__ void k_warp_sum(const float* __restrict__ motions, float* __restrict__ out)
{
    int idx = blockIdx.x * blockDim.x + threadIdx.x;   // x*NXD + y
    if (idx >= NPIX) return;
    int x = idx / NXD;
    int y = idx - x * NXD;

    float accr = 0.f, acci = 0.f;
    #pragma unroll
    for (int t = 0; t < NFRAME; t++) {
        float fx = (float)x + motions[(idx*2 + 0)*NFRAME + t];
        float fy = (float)y + motions[(idx*2 + 1)*NFRAME + t];
        fx = fminf(fmaxf(fx, 0.0f), (float)(NXD-1));
        fy = fminf(fmaxf(fy, 0.0f), (float)(NXD-1));
        int x0 = (int)floorf(fx);
        int y0 = (int)floorf(fy);
        int x1 = min(x0 + 1, NXD-1);
        int y1 = min(y0 + 1, NXD-1);
        float dx = fx - (float)x0;
        float dy = fy - (float)y0;
        const float2* im = d_imt + (size_t)t * NPIX;
        float2 v00 = im[x0*NXD + y0];
        float2 v10 = im[x1*NXD + y0];
        float2 v01 = im[x0*NXD + y1];
        float2 v11 = im[x1*NXD + y1];
        float w00 = (1.f-dx)*(1.f-dy), w10 = dx*(1.f-dy), w01 = (1.f-dx)*dy, w11 = dx*dy;
        accr += w00*v00.x + w10*v10.x + w01*v01.x + w11*v11.x;
        acci += w00*v00.y + w10*v10.y + w01*v01.y + w11*v11.y;
    }
    out[idx*2 + 0] = accr;
    out[idx*2 + 1] = acci;
}

// ---------------- launch ----------------
extern "C" void kernel_launch(void* const* d_in, const int* in_sizes, int n_in,
                              void* d_out, int out_size)
{
    const float* ksr     = (const float*)d_in[0];
    const float* ksi     = (const float*)d_in[1];
    const float* traj    = (const float*)d_in[2];
    const float* csr     = (const float*)d_in[3];
    const float* csi     = (const float*)d_in[4];
    const float* dcf     = (const float*)d_in[5];
    const float* motions = (const float*)d_in[6];
    float* out = (float*)d_out;

    const int nzero = NFRAME*NCOIL*GD*GD/2 + NFRAME*NPIX/2;   // float4 elements
    k_set_csm<<<1, 1>>>(csr, csi);
    k_zero_all<<<(nzero + 255)/256, 256>>>();
    k_scatter<<<(NFRAME*MS + 255)/256, 256>>>(ksr, ksi, traj, dcf);
    k_fft_pass1<<<NFRAME*GD*2, 320>>>();
    k_fft_pass2<<<NFRAME*2*(NXD/4), 320>>>();
    k_warp_sum<<<(NPIX + 255)/256, 256>>>(motions, out);
}

// round 12
// speedup vs baseline: 1.0423x; 1.0423x over previous
#include <cuda_runtime.h>
#include <cuda_bf16.h>
#include <math.h>

// Problem constants
#define NXD 320
#define GD  640            // OS*NX
#define NCOIL 8
#define NFRAME 8
#define MS 65536
#define NPIX (NXD*NXD)     // 102400

#define PADI8(i) ((i) + ((i) >> 3))
#define NP8 728            // PADI8(639)=718, padded to 728 (mod 32 == 24)
#define ACCS 328           // acc row stride (mod 32 == 8) -> conflict-free

// Scratch (allocations are forbidden -> __device__ globals)
__device__ float4 d_grid4[(size_t)NFRAME*GD*GD*NCOIL/2];   // ~210 MB  [t][i][j][coil]
__device__ float2 d_tmp1[(size_t)NFRAME*NCOIL*GD*NXD];     // ~105 MB  [img][r][j]
__device__ float2 d_imt[NFRAME*NPIX];                      // 8 x 320 x 320 (red-accumulated)

__device__ const float* c_csr;
__device__ const float* c_csi;

// ---------------- radix-8 butterfly (sign +i) ----------------
#define RADIX8_BODY() \
    float t0r=a0r+a4r, t0i=a0i+a4i; \
    float t1r=a0r-a4r, t1i=a0i-a4i; \
    float t2r=a2r+a6r, t2i=a2i+a6i; \
    float t3r=a2r-a6r, t3i=a2i-a6i; \
    float E0r=t0r+t2r, E0i=t0i+t2i; \
    float E2r=t0r-t2r, E2i=t0i-t2i; \
    float E1r=t1r-t3i, E1i=t1i+t3r; \
    float E3r=t1r+t3i, E3i=t1i-t3r; \
    float u0r=a1r+a5r, u0i=a1i+a5i; \
    float u1r=a1r-a5r, u1i=a1i-a5i; \
    float u2r=a3r+a7r, u2i=a3i+a7i; \
    float u3r=a3r-a7r, u3i=a3i-a7i; \
    float O0r=u0r+u2r, O0i=u0i+u2i; \
    float O2r=u0r-u2r, O2i=u0i-u2i; \
    float O1r=u1r-u3i, O1i=u1i+u3r; \
    float O3r=u1r+u3i, O3i=u1i-u3r; \
    const float RS2 = 0.70710678118654752440f; \
    float W1r = RS2*(O1r - O1i), W1i = RS2*(O1r + O1i); \
    float W2r = -O2i,            W2i = O2r; \
    float W3r = -RS2*(O3r + O3i), W3i = RS2*(O3r - O3i); \
    float b0r=E0r+O0r, b0i=E0i+O0i, b4r=E0r-O0r, b4i=E0i-O0i; \
    float b1r=E1r+W1r, b1i=E1i+W1i, b5r=E1r-W1r, b5i=E1i-W1i; \
    float b2r=E2r+W2r, b2i=E2i+W2i, b6r=E2r-W2r, b6i=E2i-W2i; \
    float b3r=E3r+W3r, b3i=E3i+W3i, b7r=E3r-W3r, b7i=E3i-W3i;

#define CMULW(br,bi,cr,ci, outr,outi) { outr = br*cr - bi*ci; outi = br*ci + bi*cr; }

// ---------------- stage 1: radix-8, S=1, n=640 ----------------
__device__ __forceinline__ void s1_r8(const float* __restrict__ sr, const float* __restrict__ si,
                                      float* __restrict__ dr, float* __restrict__ di, int lt)
{
    float a0r=sr[PADI8(lt)],     a0i=si[PADI8(lt)];
    float a1r=sr[PADI8(lt+80)],  a1i=si[PADI8(lt+80)];
    float a2r=sr[PADI8(lt+160)], a2i=si[PADI8(lt+160)];
    float a3r=sr[PADI8(lt+240)], a3i=si[PADI8(lt+240)];
    float a4r=sr[PADI8(lt+320)], a4i=si[PADI8(lt+320)];
    float a5r=sr[PADI8(lt+400)], a5i=si[PADI8(lt+400)];
    float a6r=sr[PADI8(lt+480)], a6i=si[PADI8(lt+480)];
    float a7r=sr[PADI8(lt+560)], a7i=si[PADI8(lt+560)];
    RADIX8_BODY();

    float base = 6.2831853071795864769f * (1.0f/640.0f) * (float)lt;
    float c1,s1;  __sincosf(base, &s1, &c1);
    float c2=c1*c1-s1*s1, s2=2.0f*c1*s1;
    float c3=c1*c2-s1*s2, s3=c1*s2+s1*c2;
    float c4=c2*c2-s2*s2, s4=2.0f*c2*s2;
    float c5=c2*c3-s2*s3, s5=c2*s3+s2*c3;
    float c6=c3*c3-s3*s3, s6=2.0f*c3*s3;
    float c7=c3*c4-s3*s4, s7=c3*s4+s3*c4;

    int w = 8*lt;
    float xr, xi;
    dr[PADI8(w)]   = b0r;  di[PADI8(w)]   = b0i;
    CMULW(b1r,b1i,c1,s1,xr,xi); dr[PADI8(w+1)] = xr; di[PADI8(w+1)] = xi;
    CMULW(b2r,b2i,c2,s2,xr,xi); dr[PADI8(w+2)] = xr; di[PADI8(w+2)] = xi;
    CMULW(b3r,b3i,c3,s3,xr,xi); dr[PADI8(w+3)] = xr; di[PADI8(w+3)] = xi;
    CMULW(b4r,b4i,c4,s4,xr,xi); dr[PADI8(w+4)] = xr; di[PADI8(w+4)] = xi;
    CMULW(b5r,b5i,c5,s5,xr,xi); dr[PADI8(w+5)] = xr; di[PADI8(w+5)] = xi;
    CMULW(b6r,b6i,c6,s6,xr,xi); dr[PADI8(w+6)] = xr; di[PADI8(w+6)] = xi;
    CMULW(b7r,b7i,c7,s7,xr,xi); dr[PADI8(w+7)] = xr; di[PADI8(w+7)] = xi;
}

// ---------------- stage 2: radix-8, S=8, n=80 ----------------
__device__ __forceinline__ void s2_r8(const float* __restrict__ sr, const float* __restrict__ si,
                                      float* __restrict__ dr, float* __restrict__ di, int lt)
{
    int q = lt & 7, p = lt >> 3;
    float a0r=sr[PADI8(lt)],     a0i=si[PADI8(lt)];
    float a1r=sr[PADI8(lt+80)],  a1i=si[PADI8(lt+80)];
    float a2r=sr[PADI8(lt+160)], a2i=si[PADI8(lt+160)];
    float a3r=sr[PADI8(lt+240)], a3i=si[PADI8(lt+240)];
    float a4r=sr[PADI8(lt+320)], a4i=si[PADI8(lt+320)];
    float a5r=sr[PADI8(lt+400)], a5i=si[PADI8(lt+400)];
    float a6r=sr[PADI8(lt+480)], a6i=si[PADI8(lt+480)];
    float a7r=sr[PADI8(lt+560)], a7i=si[PADI8(lt+560)];
    RADIX8_BODY();

    float base = 6.2831853071795864769f * (1.0f/80.0f) * (float)p;
    float c1,s1;  __sincosf(base, &s1, &c1);
    float c2=c1*c1-s1*s1, s2=2.0f*c1*s1;
    float c3=c1*c2-s1*s2, s3=c1*s2+s1*c2;
    float c4=c2*c2-s2*s2, s4=2.0f*c2*s2;
    float c5=c2*c3-s2*s3, s5=c2*s3+s2*c3;
    float c6=c3*c3-s3*s3, s6=2.0f*c3*s3;
    float c7=c3*c4-s3*s4, s7=c3*s4+s3*c4;

    int w = 64*p + q;
    float xr, xi;
    dr[PADI8(w)]    = b0r;  di[PADI8(w)]    = b0i;
    CMULW(b1r,b1i,c1,s1,xr,xi); dr[PADI8(w+8)]  = xr; di[PADI8(w+8)]  = xi;
    CMULW(b2r,b2i,c2,s2,xr,xi); dr[PADI8(w+16)] = xr; di[PADI8(w+16)] = xi;
    CMULW(b3r,b3i,c3,s3,xr,xi); dr[PADI8(w+24)] = xr; di[PADI8(w+24)] = xi;
    CMULW(b4r,b4i,c4,s4,xr,xi); dr[PADI8(w+32)] = xr; di[PADI8(w+32)] = xi;
    CMULW(b5r,b5i,c5,s5,xr,xi); dr[PADI8(w+40)] = xr; di[PADI8(w+40)] = xi;
    CMULW(b6r,b6i,c6,s6,xr,xi); dr[PADI8(w+48)] = xr; di[PADI8(w+48)] = xi;
    CMULW(b7r,b7i,c7,s7,xr,xi); dr[PADI8(w+56)] = xr; di[PADI8(w+56)] = xi;
}

// ---------------- stage 3: radix-10, S=64, twiddle-free ----------------
#define DFT5M(x0r,x0i,x1r,x1i,x2r,x2i,x3r,x3i,x4r,x4i, X0r,X0i,X1r,X1i,X2r,X2i,X3r,X3i,X4r,X4i) { \
    const float C1 =  0.3090169943749474241f; \
    const float S1 =  0.9510565162951535721f; \
    const float C2 = -0.8090169943749474241f; \
    const float S2 =  0.5877852522924731292f; \
    float t1r=x1r+x4r, t1i=x1i+x4i, t2r=x1r-x4r, t2i=x1i-x4i; \
    float t3r=x2r+x3r, t3i=x2i+x3i, t4r=x2r-x3r, t4i=x2i-x3i; \
    X0r = x0r + t1r + t3r;  X0i = x0i + t1i + t3i; \
    float m1r = x0r + C1*t1r + C2*t3r, m1i = x0i + C1*t1i + C2*t3i; \
    float m2r = x0r + C2*t1r + C1*t3r, m2i = x0i + C2*t1i + C1*t3i; \
    float n1r = S1*t2r + S2*t4r, n1i = S1*t2i + S2*t4i; \
    float n2r = S2*t2r - S1*t4r, n2i = S2*t2i - S1*t4i; \
    X1r = m1r - n1i;  X1i = m1i + n1r; \
    X4r = m1r + n1i;  X4i = m1i - n1r; \
    X2r = m2r - n2i;  X2i = m2i + n2r; \
    X3r = m2r + n2i;  X3i = m2i - n2r; \
}

#define STAGE3_LOAD_AND_BFLY() \
    float a0r=sr[PADI8(lt)],     a0i=si[PADI8(lt)]; \
    float a1r=sr[PADI8(lt+64)],  a1i=si[PADI8(lt+64)]; \
    float a2r=sr[PADI8(lt+128)], a2i=si[PADI8(lt+128)]; \
    float a3r=sr[PADI8(lt+192)], a3i=si[PADI8(lt+192)]; \
    float a4r=sr[PADI8(lt+256)], a4i=si[PADI8(lt+256)]; \
    float a5r=sr[PADI8(lt+320)], a5i=si[PADI8(lt+320)]; \
    float a6r=sr[PADI8(lt+384)], a6i=si[PADI8(lt+384)]; \
    float a7r=sr[PADI8(lt+448)], a7i=si[PADI8(lt+448)]; \
    float a8r=sr[PADI8(lt+512)], a8i=si[PADI8(lt+512)]; \
    float a9r=sr[PADI8(lt+576)], a9i=si[PADI8(lt+576)]; \
    float E0r,E0i,E1r,E1i,E2r,E2i,E3r,E3i,E4r,E4i; \
    float O0r,O0i,O1r,O1i,O2r,O2i,O3r,O3i,O4r,O4i; \
    DFT5M(a0r,a0i,a2r,a2i,a4r,a4i,a6r,a6i,a8r,a8i, E0r,E0i,E1r,E1i,E2r,E2i,E3r,E3i,E4r,E4i); \
    DFT5M(a1r,a1i,a3r,a3i,a5r,a5i,a7r,a7i,a9r,a9i, O0r,O0i,O1r,O1i,O2r,O2i,O3r,O3i,O4r,O4i); \
    const float W1R=0.8090169943749474241f,  W1I=0.5877852522924731292f; \
    const float W2R=0.3090169943749474241f,  W2I=0.9510565162951535721f; \
    const float W3R=-0.3090169943749474241f, W3I=0.9510565162951535721f; \
    const float W4R=-0.8090169943749474241f, W4I=0.5877852522924731292f; \
    float P1r,P1i,P2r,P2i,P3r,P3i,P4r,P4i; \
    CMULW(O1r,O1i,W1R,W1I,P1r,P1i); \
    CMULW(O2r,O2i,W2R,W2I,P2r,P2i); \
    CMULW(O3r,O3i,W3R,W3I,P3r,P3i); \
    CMULW(O4r,O4i,W4R,W4I,P4r,P4i); \
    float b0r=E0r+O0r, b0i=E0i+O0i; \
    float b1r=E1r+P1r, b1i=E1i+P1i; \
    float b2r=E2r+P2r, b2i=E2i+P2i; \
    float b7r=E2r-P2r, b7i=E2i-P2i; \
    float b8r=E3r-P3r, b8i=E3i-P3i; \
    float b9r=E4r-P4r, b9i=E4i-P4i;

// deapodization inverse factor: 1/sinc^2((i-160)/640)
__device__ __forceinline__ float deapod_inv(int i)
{
    if (i == 160) return 1.0f;
    float px = 3.14159265358979324f * (float)(i - 160) * (1.0f/640.0f);
    float s = __sinf(px);
    float r = px / s;
    return r * r;
}

// ---------------- kernels ----------------
__global__ void k_set_csm(const float* csr, const float* csi)
{
    c_csr = csr;  c_csi = csi;
}

__global__ void k_zero_all()
{
    unsigned i = blockIdx.x * blockDim.x + threadIdx.x;
    const unsigned n1 = (unsigned)(NFRAME*NCOIL) * GD * GD / 2;   // grid float4s
    const unsigned n2 = (unsigned)NFRAME * NPIX / 2;              // d_imt float4s
    if (i < n1) d_grid4[i] = make_float4(0.f,0.f,0.f,0.f);
    else if (i < n1 + n2) reinterpret_cast<float4*>(d_imt)[i - n1] = make_float4(0.f,0.f,0.f,0.f);
}

__device__ __forceinline__ void red_v4(float* p, float a, float b, float c, float d)
{
    asm volatile("red.global.add.v4.f32 [%0], {%1, %2, %3, %4};"
                 :: "l"(p), "f"(a), "f"(b), "f"(c), "f"(d) : "memory");
}
__device__ __forceinline__ void red_v2(float2* p, float re, float im)
{
    asm volatile("red.global.add.v2.f32 [%0], {%1, %2};" :: "l"(p), "f"(re), "f"(im) : "memory");
}

__global__ void k_scatter(const float* __restrict__ ksr, const float* __restrict__ ksi,
                          const float* __restrict__ traj, const float* __restrict__ dcf)
{
    int idx = blockIdx.x * blockDim.x + threadIdx.x;   // t*MS + m
    if (idx >= NFRAME * MS) return;
    int t = idx >> 16;
    int m = idx & (MS - 1);

    float u = (traj[m*2*NFRAME + 0*NFRAME + t] + 0.5f) * (float)GD;
    float v = (traj[m*2*NFRAME + 1*NFRAME + t] + 0.5f) * (float)GD;
    float w = dcf[m*NFRAME + t];

    float u0f = floorf(u), v0f = floorf(v);
    float du = u - u0f, dv = v - v0f;
    int i0 = (int)u0f; if (i0 >= GD) i0 -= GD;
    int j0 = (int)v0f; if (j0 >= GD) j0 -= GD;
    int i1 = i0 + 1; if (i1 >= GD) i1 -= GD;
    int j1 = j0 + 1; if (j1 >= GD) j1 -= GD;

    float wc[4];
    wc[0] = (1.0f-du)*(1.0f-dv)*w;
    wc[1] = du*(1.0f-dv)*w;
    wc[2] = (1.0f-du)*dv*w;
    wc[3] = du*dv*w;
    size_t oc[4];
    oc[0] = ((size_t)i0*GD + j0) * NCOIL;
    oc[1] = ((size_t)i1*GD + j0) * NCOIL;
    oc[2] = ((size_t)i0*GD + j1) * NCOIL;
    oc[3] = ((size_t)i1*GD + j1) * NCOIL;

    float kr[NCOIL], ki[NCOIL];
    #pragma unroll
    for (int c = 0; c < NCOIL; c++) { kr[c] = ksr[c*MS + m]; ki[c] = ksi[c*MS + m]; }

    float* gbase = (float*)(d_grid4) + (size_t)t * GD * GD * NCOIL * 2;
    #pragma unroll
    for (int k = 0; k < 4; k++) {
        float* p = gbase + oc[k]*2;
        float ww = wc[k];
        #pragma unroll
        for (int h = 0; h < 4; h++) {
            red_v4(p + 4*h, kr[2*h]*ww, ki[2*h]*ww, kr[2*h+1]*ww, ki[2*h+1]*ww);
        }
    }
}

// Pass 1: block = (t, row r, coil-group cg of 4). 4 concurrent 640-pt FFTs
// along j. Stage 3 streams cropped+shifted rows directly to global.
__global__ void __launch_bounds__(320, 3) k_fft_pass1()
{
    __shared__ float cR[4][NP8], cI[4][NP8];
    __shared__ float pR[4][NP8], pI[4][NP8];
    int b = blockIdx.x;
    int cg = b & 1;
    int tr = b >> 1;
    int t  = tr / GD;
    int r  = tr - t * GD;
    int tid = threadIdx.x;

    const float2* row = (const float2*)d_grid4 + ((size_t)(t*GD + r) * GD) * NCOIL + 4*cg;
    #pragma unroll
    for (int it = 0; it < 8; it++) {
        int idx = it * 320 + tid;
        int j  = idx >> 2;
        int cl = idx & 3;
        int jsh = (j < NXD) ? (j + NXD) : (j - NXD);
        float2 v = row[(size_t)j * NCOIL + cl];
        cR[cl][PADI8(jsh)] = v.x;  cI[cl][PADI8(jsh)] = v.y;
    }
    __syncthreads();

    int f  = tid / 80;
    int lt = tid - f * 80;

    s1_r8(cR[f], cI[f], pR[f], pI[f], lt);
    __syncthreads();
    s2_r8(pR[f], pI[f], cR[f], cI[f], lt);
    __syncthreads();

    if (lt < 64) {
        const float* sr = cR[f];
        const float* si = cI[f];
        STAGE3_LOAD_AND_BFLY();
        int c = 4*cg + f;
        float2* orow = d_tmp1 + ((size_t)(t*NCOIL + c) * GD + r) * NXD;
        orow[lt+160] = make_float2(b0r, b0i);                 // k=0
        orow[lt+224] = make_float2(b1r, b1i);                 // k=1
        if (lt < 32)  orow[lt+288] = make_float2(b2r, b2i);   // k=2
        if (lt >= 32) orow[lt-32]  = make_float2(b7r, b7i);   // k=7
        orow[lt+32]  = make_float2(b8r, b8i);                 // k=8
        orow[lt+96]  = make_float2(b9r, b9i);                 // k=9
    }
}

// Pass 2 FUSED v2: block = (t, coil-pair cp, 4 columns). Dynamic smem:
// FFT buffers + csm staging (reuses ping) + SHARED accumulators (no reg
// pressure, no uncoalesced csm loads). 2560 blocks -> 9% tail.
__global__ void __launch_bounds__(320, 3) k_fft_pass2()
{
    extern __shared__ float sm[];
    float* cRb = sm;                 // 4*NP8
    float* cIb = sm + 4*NP8;
    float* pRb = sm + 8*NP8;
    float* pIb = sm + 12*NP8;
    float* aRb = sm + 16*NP8;        // 4*ACCS
    float* aIb = sm + 16*NP8 + 4*ACCS;

    int b  = blockIdx.x;
    int cp = b & 3;                      // coil pair: coils cp*2, cp*2+1
    int jp = (b >> 2) % (NXD/4);
    int t  = b / (4*(NXD/4));
    int jb = jp * 4;
    int tid = threadIdx.x;
    int f  = tid / 80;
    int lt = tid - f * 80;

    // Zero shared accumulators (4*ACCS*2 = 2624 floats).
    for (int i = tid; i < 4*ACCS; i += 320) { aRb[i] = 0.f; aIb[i] = 0.f; }
    __syncthreads();

    int i0 = lt + 160, i1 = lt + 224, i4 = lt + 32, i5 = lt + 96;
    int i2 = (lt < 32) ? (lt + 288) : (lt - 32);

    #pragma unroll 1
    for (int it = 0; it < 2; it++) {
        int c = cp*2 + it;

        // Coalesced tile load (4 cols of coil c) with ifftshift on rows.
        const float2* base = d_tmp1 + ((size_t)(t*NCOIL + c) * GD) * NXD + jb;
        #pragma unroll
        for (int k = 0; k < 8; k++) {
            int idx = k * 320 + tid;
            int rr = idx >> 2;
            int cl = idx & 3;
            int rsh = (rr < NXD) ? (rr + NXD) : (rr - NXD);
            float2 v = base[(size_t)rr * NXD + cl];
            cRb[cl*NP8 + PADI8(rsh)] = v.x;  cIb[cl*NP8 + PADI8(rsh)] = v.y;
        }
        __syncthreads();

        s1_r8(cRb + f*NP8, cIb + f*NP8, pRb + f*NP8, pIb + f*NP8, lt);
        __syncthreads();
        s2_r8(pRb + f*NP8, pIb + f*NP8, cRb + f*NP8, cIb + f*NP8, lt);
        __syncthreads();

        // Stage csm tile (coil c, 4 cols x 320 rows) into the free ping buffers.
        {
            const float* gr = c_csr + (size_t)c * NPIX + jb;
            const float* gi = c_csi + (size_t)c * NPIX + jb;
            #pragma unroll
            for (int k = 0; k < 4; k++) {
                int idx = k * 320 + tid;
                int i  = idx >> 2;
                int cl = idx & 3;
                pRb[cl*NP8 + PADI8(i)] = gr[(size_t)i * NXD + cl];
                pIb[cl*NP8 + PADI8(i)] = gi[(size_t)i * NXD + cl];
            }
        }
        __syncthreads();

        if (lt < 64) {
            const float* sr = cRb + f*NP8;
            const float* si = cIb + f*NP8;
            STAGE3_LOAD_AND_BFLY();
            const float* cmr = pRb + f*NP8;
            const float* cmi = pIb + f*NP8;
            float* aR = aRb + f*ACCS;
            float* aI = aIb + f*ACCS;
            float cr, ci;
            cr = cmr[PADI8(i0)]; ci = cmi[PADI8(i0)];
            aR[i0] += cr*b0r + ci*b0i;  aI[i0] += cr*b0i - ci*b0r;
            cr = cmr[PADI8(i1)]; ci = cmi[PADI8(i1)];
            aR[i1] += cr*b1r + ci*b1i;  aI[i1] += cr*b1i - ci*b1r;
            cr = cmr[PADI8(i2)]; ci = cmi[PADI8(i2)];
            if (lt < 32) { aR[i2] += cr*b2r + ci*b2i;  aI[i2] += cr*b2i - ci*b2r; }
            else         { aR[i2] += cr*b7r + ci*b7i;  aI[i2] += cr*b7i - ci*b7r; }
            cr = cmr[PADI8(i4)]; ci = cmi[PADI8(i4)];
            aR[i4] += cr*b8r + ci*b8i;  aI[i4] += cr*b8i - ci*b8r;
            cr = cmr[PADI8(i5)]; ci = cmi[PADI8(i5)];
            aR[i5] += cr*b9r + ci*b9i;  aI[i5] += cr*b9i - ci*b9r;
        }
        __syncthreads();   // protect cR/pR before next coil
    }

    // Deapod + 1/(G*G) scale, coalesced red-add into d_imt.
    float2* obase = d_imt + (size_t)t * NPIX + jb;
    #pragma unroll
    for (int k = 0; k < 4; k++) {
        int idx = k * 320 + tid;
        int i  = idx >> 2;
        int cl = idx & 3;
        float s = (1.0f/409600.0f) * deapod_inv(i) * deapod_inv(jb + cl);
        red_v2(&obase[(size_t)i * NXD + cl], aRb[cl*ACCS + i]*s, aIb[cl*ACCS + i]*s);
    }
}

// Motion warp each frame and sum over frames.
__global__ void k_warp_sum(const float* __restrict__ motions, float* __restrict__ out)
{
    int idx = blockIdx.x * blockDim.x + threadIdx.x;   // x*NXD + y
    if (idx >= NPIX) return;
    int x = idx / NXD;
    int y = idx - x * NXD;

    float accr = 0.f, acci = 0.f;
    #pragma unroll
    for (int t = 0; t < NFRAME; t++) {
        float fx = (float)x + motions[(idx*2 + 0)*NFRAME + t];
        float fy = (float)y + motions[(idx*2 + 1)*NFRAME + t];
        fx = fminf(fmaxf(fx, 0.0f), (float)(NXD-1));
        fy = fminf(fmaxf(fy, 0.0f), (float)(NXD-1));
        int x0 = (int)floorf(fx);
        int y0 = (int)floorf(fy);
        int x1 = min(x0 + 1, NXD-1);
        int y1 = min(y0 + 1, NXD-1);
        float dx = fx - (float)x0;
        float dy = fy - (float)y0;
        const float2* im = d_imt + (size_t)t * NPIX;
        float2 v00 = im[x0*NXD + y0];
        float2 v10 = im[x1*NXD + y0];
        float2 v01 = im[x0*NXD + y1];
        float2 v11 = im[x1*NXD + y1];
        float w00 = (1.f-dx)*(1.f-dy), w10 = dx*(1.f-dy), w01 = (1.f-dx)*dy, w11 = dx*dy;
        accr += w00*v00.x + w10*v10.x + w01*v01.x + w11*v11.x;
        acci += w00*v00.y + w10*v10.y + w01*v01.y + w11*v11.y;
    }
    out[idx*2 + 0] = accr;
    out[idx*2 + 1] = acci;
}

// ---------------- launch ----------------
extern "C" void kernel_launch(void* const* d_in, const int* in_sizes, int n_in,
                              void* d_out, int out_size)
{
    const float* ksr     = (const float*)d_in[0];
    const float* ksi     = (const float*)d_in[1];
    const float* traj    = (const float*)d_in[2];
    const float* csr     = (const float*)d_in[3];
    const float* csi     = (const float*)d_in[4];
    const float* dcf     = (const float*)d_in[5];
    const float* motions = (const float*)d_in[6];
    float* out = (float*)d_out;

    const int smem_p2 = (16*NP8 + 8*ACCS) * sizeof(float);   // 57088 B
    cudaFuncSetAttribute(k_fft_pass2, cudaFuncAttributeMaxDynamicSharedMemorySize, smem_p2);

    const int nzero = NFRAME*NCOIL*GD*GD/2 + NFRAME*NPIX/2;   // float4 elements
    k_set_csm<<<1, 1>>>(csr, csi);
    k_zero_all<<<(nzero + 255)/256, 256>>>();
    k_scatter<<<(NFRAME*MS + 255)/256, 256>>>(ksr, ksi, traj, dcf);
    k_fft_pass1<<<NFRAME*GD*2, 320>>>();
    k_fft_pass2<<<NFRAME*4*(NXD/4), 320, smem_p2>>>();
    k_warp_sum<<<(NPIX + 255)/256, 256>>>(motions, out);
}